// round 1
// baseline (speedup 1.0000x reference)
#include <cuda_runtime.h>
#include <cuda_bf16.h>
#include <math.h>

// ---------------- problem constants ----------------
#define LAYERS 12
#define DIM    726
#define NHEAD  16
#define HDIM   45
#define HH     (NHEAD*HDIM)   // 720
#define TT     258
#define BB     16
#define MM     (BB*TT)        // 4128
#define FF     (4*DIM)        // 2904
#define VOCAB  50257

// ---------------- scratch (device globals; no allocation allowed) ----------------
__device__ float g_x [MM*DIM];   // residual stream
__device__ float g_h [MM*DIM];   // LN output
__device__ float g_q [MM*HH];
__device__ float g_k [MM*HH];
__device__ float g_v [MM*HH];
__device__ float g_o [MM*HH];
__device__ float g_ff[MM*FF];

// ---------------- embedding ----------------
__global__ void embed_kernel(const int* __restrict__ idx,
                             const float* __restrict__ tok,
                             const float* __restrict__ pos,
                             float* __restrict__ x)
{
    int i = blockIdx.x * blockDim.x + threadIdx.x;
    if (i >= MM * DIM) return;
    int m = i / DIM, d = i - m * DIM;
    int t = m % TT;
    x[i] = tok[idx[m] * DIM + d] + pos[t * DIM + d];
}

// ---------------- layernorm: one block per row ----------------
__global__ void ln_kernel(const float* __restrict__ x,
                          const float* __restrict__ g,
                          const float* __restrict__ b,
                          float* __restrict__ h)
{
    int m = blockIdx.x;
    const float* row = x + (size_t)m * DIM;
    int tid = threadIdx.x;
    float s = 0.f, sq = 0.f;
    for (int d = tid; d < DIM; d += 256) {
        float v = row[d];
        s += v; sq += v * v;
    }
    __shared__ float r1[256], r2[256];
    r1[tid] = s; r2[tid] = sq;
    __syncthreads();
    for (int off = 128; off > 0; off >>= 1) {
        if (tid < off) { r1[tid] += r1[tid + off]; r2[tid] += r2[tid + off]; }
        __syncthreads();
    }
    float mean = r1[0] * (1.0f / DIM);
    float var  = r2[0] * (1.0f / DIM) - mean * mean;
    float rs   = rsqrtf(var + 1e-5f);
    for (int d = tid; d < DIM; d += 256)
        h[(size_t)m * DIM + d] = (row[d] - mean) * rs * g[d] + b[d];
}

// ---------------- generic tiled SGEMM with fused epilogue ----------------
// C[m,n] = sum_k A[m,k] * B(k,n)  (+bias[n]) (+res[m,n]) (relu)
// bmode 0: B row-major [K,N]
// bmode 1: QKV head layout: B[(h*DIM + k)*HDIM + kk], n = h*HDIM + kk
__global__ void gemm_kernel(const float* __restrict__ A,
                            const float* __restrict__ Bm,
                            const float* __restrict__ bias,
                            const float* __restrict__ res,
                            float* __restrict__ C,
                            int M, int N, int K, int bmode, int relu)
{
    __shared__ float As[16][64];
    __shared__ float Bs[16][64];

    int tid = threadIdx.x;
    int tx = tid & 15, ty = tid >> 4;
    int rm = blockIdx.y * 64, cn = blockIdx.x * 64;

    float acc[4][4];
#pragma unroll
    for (int i = 0; i < 4; i++)
#pragma unroll
        for (int j = 0; j < 4; j++) acc[i][j] = 0.f;

    for (int kb = 0; kb < K; kb += 16) {
        // load A tile (64 rows x 16 k), store transposed As[k][m]
#pragma unroll
        for (int i = 0; i < 4; i++) {
            int lin = tid + 256 * i;
            int r = lin >> 4, c = lin & 15;
            int gm = rm + r, gk = kb + c;
            As[c][r] = (gm < M && gk < K) ? A[(size_t)gm * K + gk] : 0.f;
        }
        // load B tile (16 k x 64 n)
#pragma unroll
        for (int i = 0; i < 4; i++) {
            int lin = tid + 256 * i;
            int r = lin >> 6, c = lin & 63;
            int gk = kb + r, gn = cn + c;
            float v = 0.f;
            if (gk < K && gn < N) {
                if (bmode == 0) {
                    v = Bm[(size_t)gk * N + gn];
                } else {
                    int h  = gn / HDIM;
                    int kk = gn - h * HDIM;
                    v = Bm[((size_t)h * DIM + gk) * HDIM + kk];
                }
            }
            Bs[r][c] = v;
        }
        __syncthreads();
#pragma unroll
        for (int k = 0; k < 16; k++) {
            float4 a4 = *(const float4*)&As[k][ty * 4];
            float4 b4 = *(const float4*)&Bs[k][tx * 4];
            float a[4] = {a4.x, a4.y, a4.z, a4.w};
            float b[4] = {b4.x, b4.y, b4.z, b4.w};
#pragma unroll
            for (int i = 0; i < 4; i++)
#pragma unroll
                for (int j = 0; j < 4; j++)
                    acc[i][j] = fmaf(a[i], b[j], acc[i][j]);
        }
        __syncthreads();
    }

#pragma unroll
    for (int i = 0; i < 4; i++) {
        int m = rm + ty * 4 + i;
        if (m >= M) continue;
#pragma unroll
        for (int j = 0; j < 4; j++) {
            int n = cn + tx * 4 + j;
            if (n >= N) continue;
            float v = acc[i][j];
            if (bias) v += bias[n];
            if (res)  v += res[(size_t)m * N + n];
            if (relu) v = fmaxf(v, 0.f);
            C[(size_t)m * N + n] = v;
        }
    }
}

// ---------------- fused causal attention (scores + softmax + AV) ----------------
// one block per (t, h, b); q/k/v/o stored as [M, HH] with column h*HDIM+kk
__global__ void attn_kernel(const float* __restrict__ q,
                            const float* __restrict__ k,
                            const float* __restrict__ v,
                            float* __restrict__ o)
{
    int t = blockIdx.x, h = blockIdx.y, b = blockIdx.z;
    int tid = threadIdx.x;

    __shared__ float sc[TT];
    __shared__ float red[128];
    __shared__ float qs[HDIM];

    const float scale = rsqrtf((float)HDIM);
    size_t rowq = ((size_t)b * TT + t) * HH + h * HDIM;

    if (tid < HDIM) qs[tid] = q[rowq + tid];
    __syncthreads();

    // scores for s <= t
    for (int s = tid; s <= t; s += 128) {
        const float* krow = k + ((size_t)b * TT + s) * HH + h * HDIM;
        float d = 0.f;
#pragma unroll
        for (int kk = 0; kk < HDIM; kk++) d = fmaf(qs[kk], krow[kk], d);
        sc[s] = d * scale;
    }
    __syncthreads();

    // max
    float mx = -1e30f;
    for (int s = tid; s <= t; s += 128) mx = fmaxf(mx, sc[s]);
    red[tid] = mx;
    __syncthreads();
    for (int off = 64; off > 0; off >>= 1) {
        if (tid < off) red[tid] = fmaxf(red[tid], red[tid + off]);
        __syncthreads();
    }
    float gmax = red[0];
    __syncthreads();

    // exp + sum
    float sum = 0.f;
    for (int s = tid; s <= t; s += 128) {
        float e = expf(sc[s] - gmax);
        sc[s] = e;
        sum += e;
    }
    red[tid] = sum;
    __syncthreads();
    for (int off = 64; off > 0; off >>= 1) {
        if (tid < off) red[tid] += red[tid + off];
        __syncthreads();
    }
    float inv = 1.f / red[0];
    __syncthreads();

    // o[kk] = sum_s p[s] * v[s,kk]
    for (int kk = tid; kk < HDIM; kk += 128) {
        float acc = 0.f;
        for (int s = 0; s <= t; s++)
            acc = fmaf(sc[s], v[((size_t)b * TT + s) * HH + h * HDIM + kk], acc);
        o[rowq + kk] = acc * inv;
    }
}

// ---------------- host side ----------------
static void launch_gemm(const float* A, const float* B, const float* bias,
                        const float* res, float* C,
                        int M, int N, int K, int bmode, int relu)
{
    dim3 grid((N + 63) / 64, (M + 63) / 64);
    gemm_kernel<<<grid, 256>>>(A, B, bias, res, C, M, N, K, bmode, relu);
}

extern "C" void kernel_launch(void* const* d_in, const int* in_sizes, int n_in,
                              void* d_out, int out_size)
{
    const int*   idx    = (const int*)  d_in[0];
    const float* tok    = (const float*)d_in[1];
    const float* pos    = (const float*)d_in[2];
    const float* Wq     = (const float*)d_in[3];
    const float* Wk     = (const float*)d_in[4];
    const float* Wv     = (const float*)d_in[5];
    const float* Wproj  = (const float*)d_in[6];
    const float* bproj  = (const float*)d_in[7];
    const float* ln1_g  = (const float*)d_in[8];
    const float* ln1_b  = (const float*)d_in[9];
    const float* ln2_g  = (const float*)d_in[10];
    const float* ln2_b  = (const float*)d_in[11];
    const float* W1     = (const float*)d_in[12];
    const float* b1     = (const float*)d_in[13];
    const float* W2     = (const float*)d_in[14];
    const float* b2     = (const float*)d_in[15];
    const float* lnf_g  = (const float*)d_in[16];
    const float* lnf_b  = (const float*)d_in[17];
    const float* Wlm    = (const float*)d_in[18];
    const float* blm    = (const float*)d_in[19];

    float *x_, *h_, *q_, *k_, *v_, *o_, *ff_;
    cudaGetSymbolAddress((void**)&x_,  g_x);
    cudaGetSymbolAddress((void**)&h_,  g_h);
    cudaGetSymbolAddress((void**)&q_,  g_q);
    cudaGetSymbolAddress((void**)&k_,  g_k);
    cudaGetSymbolAddress((void**)&v_,  g_v);
    cudaGetSymbolAddress((void**)&o_,  g_o);
    cudaGetSymbolAddress((void**)&ff_, g_ff);

    // embedding
    {
        int total = MM * DIM;
        embed_kernel<<<(total + 255) / 256, 256>>>(idx, tok, pos, x_);
    }

    for (int l = 0; l < LAYERS; l++) {
        const float* wq = Wq + (size_t)l * NHEAD * DIM * HDIM;
        const float* wk = Wk + (size_t)l * NHEAD * DIM * HDIM;
        const float* wv = Wv + (size_t)l * NHEAD * DIM * HDIM;
        const float* wp = Wproj + (size_t)l * HH * DIM;
        const float* bp = bproj + (size_t)l * DIM;
        const float* g1 = ln1_g + (size_t)l * DIM;
        const float* be1= ln1_b + (size_t)l * DIM;
        const float* g2 = ln2_g + (size_t)l * DIM;
        const float* be2= ln2_b + (size_t)l * DIM;
        const float* w1 = W1 + (size_t)l * DIM * FF;
        const float* bb1= b1 + (size_t)l * FF;
        const float* w2 = W2 + (size_t)l * FF * DIM;
        const float* bb2= b2 + (size_t)l * DIM;

        // LN1
        ln_kernel<<<MM, 256>>>(x_, g1, be1, h_);

        // q,k,v = h @ W{q,k,v}  (head-sliced weight layout)
        launch_gemm(h_, wq, nullptr, nullptr, q_, MM, HH, DIM, 1, 0);
        launch_gemm(h_, wk, nullptr, nullptr, k_, MM, HH, DIM, 1, 0);
        launch_gemm(h_, wv, nullptr, nullptr, v_, MM, HH, DIM, 1, 0);

        // fused causal attention
        {
            dim3 grid(TT, NHEAD, BB);
            attn_kernel<<<grid, 128>>>(q_, k_, v_, o_);
        }

        // x = x + o @ Wproj + bproj
        launch_gemm(o_, wp, bp, x_, x_, MM, DIM, HH, 0, 0);

        // LN2
        ln_kernel<<<MM, 256>>>(x_, g2, be2, h_);

        // ff = relu(h @ W1 + b1)
        launch_gemm(h_, w1, bb1, nullptr, ff_, MM, FF, DIM, 0, 1);

        // x = x + ff @ W2 + b2
        launch_gemm(ff_, w2, bb2, x_, x_, MM, DIM, FF, 0, 0);
    }

    // final LN
    ln_kernel<<<MM, 256>>>(x_, lnf_g, lnf_b, h_);

    // logits = h @ Wlm + blm
    launch_gemm(h_, Wlm, blm, nullptr, (float*)d_out, MM, VOCAB, DIM, 0, 0);
}

// round 2
// speedup vs baseline: 1.3898x; 1.3898x over previous
#include <cuda_runtime.h>
#include <cuda_bf16.h>
#include <mma.h>
#include <math.h>

using namespace nvcuda;

// ---------------- problem constants ----------------
#define LAYERS 12
#define DIM    726
#define NHEAD  16
#define HDIM   45
#define HH     (NHEAD*HDIM)   // 720
#define TT     258
#define BB     16
#define MM     (BB*TT)        // 4128
#define FF     (4*DIM)        // 2904
#define VOCAB  50257

// ---------------- scratch (device globals; no allocation allowed) ----------------
__device__ float g_x [MM*DIM];   // residual stream
__device__ float g_h [MM*DIM];   // LN output
__device__ float g_q [MM*HH];
__device__ float g_k [MM*HH];
__device__ float g_v [MM*HH];
__device__ float g_o [MM*HH];
__device__ float g_ff[MM*FF];

// ---------------- embedding ----------------
__global__ void embed_kernel(const int* __restrict__ idx,
                             const float* __restrict__ tok,
                             const float* __restrict__ pos,
                             float* __restrict__ x)
{
    int i = blockIdx.x * blockDim.x + threadIdx.x;
    if (i >= MM * DIM) return;
    int m = i / DIM, d = i - m * DIM;
    int t = m % TT;
    x[i] = tok[idx[m] * DIM + d] + pos[t * DIM + d];
}

// ---------------- layernorm: one block per row ----------------
__global__ void ln_kernel(const float* __restrict__ x,
                          const float* __restrict__ g,
                          const float* __restrict__ b,
                          float* __restrict__ h)
{
    int m = blockIdx.x;
    const float* row = x + (size_t)m * DIM;
    int tid = threadIdx.x;
    float s = 0.f, sq = 0.f;
    for (int d = tid; d < DIM; d += 256) {
        float v = row[d];
        s += v; sq += v * v;
    }
    __shared__ float r1[256], r2[256];
    r1[tid] = s; r2[tid] = sq;
    __syncthreads();
    for (int off = 128; off > 0; off >>= 1) {
        if (tid < off) { r1[tid] += r1[tid + off]; r2[tid] += r2[tid + off]; }
        __syncthreads();
    }
    float mean = r1[0] * (1.0f / DIM);
    float var  = r2[0] * (1.0f / DIM) - mean * mean;
    float rs   = rsqrtf(var + 1e-5f);
    for (int d = tid; d < DIM; d += 256)
        h[(size_t)m * DIM + d] = (row[d] - mean) * rs * g[d] + b[d];
}

// ---------------- tf32 tensor-core GEMM with fused epilogue ----------------
// C[m,n] = sum_k A[m,k] * B(k,n)  (+bias[n]) (+res[m,n]) (relu)
// bmode 0: B row-major [K,N]
// bmode 1: QKV head layout: B[(h*DIM + k)*HDIM + kk], n = h*HDIM + kk
//
// Block tile 128x64, 8 warps (4x2), each warp 32x32 via 2x2 m16n16k8 tf32 frags.
#define BM 128
#define BN 64
#define BK 32
#define A_LD (BK + 8)    // 40
#define B_LD (BN + 8)    // 72
#define C_LD 64
#define A_ELEMS (BM * A_LD)          // 5120
#define B_ELEMS (BK * B_LD)          // 2304
#define SMEM_FLOATS 8192             // max(A+B = 7424, C = 8192)

__global__ void __launch_bounds__(256)
gemm_tc(const float* __restrict__ A,
        const float* __restrict__ Bm,
        const float* __restrict__ bias,
        const float* __restrict__ res,
        float* __restrict__ C,
        int M, int N, int K, int bmode, int relu)
{
    __shared__ float smem[SMEM_FLOATS];
    float* As = smem;              // [BM][A_LD]
    float* Bs = smem + A_ELEMS;    // [BK][B_LD]
    float* Cs = smem;              // [BM][C_LD]  (aliases As/Bs, used after k-loop)

    int tid  = threadIdx.x;
    int warp = tid >> 5;
    int wm   = warp >> 1;          // 0..3  (M direction)
    int wn   = warp & 1;           // 0..1  (N direction)
    int rm   = blockIdx.y * BM;
    int cn   = blockIdx.x * BN;

    wmma::fragment<wmma::accumulator, 16, 16, 8, float> acc[2][2];
#pragma unroll
    for (int i = 0; i < 2; i++)
#pragma unroll
        for (int j = 0; j < 2; j++)
            wmma::fill_fragment(acc[i][j], 0.f);

    for (int kb = 0; kb < K; kb += BK) {
        // load A tile: 128 x 32, 16 elems/thread, coalesced along k
#pragma unroll
        for (int it = 0; it < 16; it++) {
            int lin = it * 256 + tid;
            int r = lin >> 5, c = lin & 31;
            int gm = rm + r, gk = kb + c;
            float v = (gm < M && gk < K) ? A[(size_t)gm * K + gk] : 0.f;
            As[r * A_LD + c] = wmma::__float_to_tf32(v);
        }
        // load B tile: 32 x 64, 8 elems/thread, coalesced along n
#pragma unroll
        for (int it = 0; it < 8; it++) {
            int lin = it * 256 + tid;
            int r = lin >> 6, c = lin & 63;
            int gk = kb + r, gn = cn + c;
            float v = 0.f;
            if (gk < K && gn < N) {
                if (bmode == 0) {
                    v = Bm[(size_t)gk * N + gn];
                } else {
                    int h  = gn / HDIM;
                    int kk = gn - h * HDIM;
                    v = Bm[((size_t)h * DIM + gk) * HDIM + kk];
                }
            }
            Bs[r * B_LD + c] = wmma::__float_to_tf32(v);
        }
        __syncthreads();

#pragma unroll
        for (int kk = 0; kk < BK; kk += 8) {
            wmma::fragment<wmma::matrix_a, 16, 16, 8, wmma::precision::tf32, wmma::row_major> af[2];
            wmma::fragment<wmma::matrix_b, 16, 16, 8, wmma::precision::tf32, wmma::row_major> bf[2];
#pragma unroll
            for (int i = 0; i < 2; i++)
                wmma::load_matrix_sync(af[i], &As[(wm * 32 + i * 16) * A_LD + kk], A_LD);
#pragma unroll
            for (int j = 0; j < 2; j++)
                wmma::load_matrix_sync(bf[j], &Bs[kk * B_LD + wn * 32 + j * 16], B_LD);
#pragma unroll
            for (int i = 0; i < 2; i++)
#pragma unroll
                for (int j = 0; j < 2; j++)
                    wmma::mma_sync(acc[i][j], af[i], bf[j], acc[i][j]);
        }
        __syncthreads();
    }

    // epilogue: stage accumulators in smem, then guarded fused store
#pragma unroll
    for (int i = 0; i < 2; i++)
#pragma unroll
        for (int j = 0; j < 2; j++)
            wmma::store_matrix_sync(&Cs[(wm * 32 + i * 16) * C_LD + wn * 32 + j * 16],
                                    acc[i][j], C_LD, wmma::mem_row_major);
    __syncthreads();

#pragma unroll
    for (int it = 0; it < 32; it++) {
        int lin = it * 256 + tid;
        int r = lin >> 6, c = lin & 63;
        int m = rm + r, n = cn + c;
        if (m < M && n < N) {
            float v = Cs[r * C_LD + c];
            if (bias) v += bias[n];
            if (res)  v += res[(size_t)m * N + n];
            if (relu) v = fmaxf(v, 0.f);
            C[(size_t)m * N + n] = v;
        }
    }
}

// ---------------- fused causal attention (scores + softmax + AV) ----------------
__global__ void attn_kernel(const float* __restrict__ q,
                            const float* __restrict__ k,
                            const float* __restrict__ v,
                            float* __restrict__ o)
{
    int t = blockIdx.x, h = blockIdx.y, b = blockIdx.z;
    int tid = threadIdx.x;

    __shared__ float sc[TT];
    __shared__ float red[128];
    __shared__ float qs[HDIM];

    const float scale = rsqrtf((float)HDIM);
    size_t rowq = ((size_t)b * TT + t) * HH + h * HDIM;

    if (tid < HDIM) qs[tid] = q[rowq + tid];
    __syncthreads();

    for (int s = tid; s <= t; s += 128) {
        const float* krow = k + ((size_t)b * TT + s) * HH + h * HDIM;
        float d = 0.f;
#pragma unroll
        for (int kk = 0; kk < HDIM; kk++) d = fmaf(qs[kk], krow[kk], d);
        sc[s] = d * scale;
    }
    __syncthreads();

    float mx = -1e30f;
    for (int s = tid; s <= t; s += 128) mx = fmaxf(mx, sc[s]);
    red[tid] = mx;
    __syncthreads();
    for (int off = 64; off > 0; off >>= 1) {
        if (tid < off) red[tid] = fmaxf(red[tid], red[tid + off]);
        __syncthreads();
    }
    float gmax = red[0];
    __syncthreads();

    float sum = 0.f;
    for (int s = tid; s <= t; s += 128) {
        float e = expf(sc[s] - gmax);
        sc[s] = e;
        sum += e;
    }
    red[tid] = sum;
    __syncthreads();
    for (int off = 64; off > 0; off >>= 1) {
        if (tid < off) red[tid] += red[tid + off];
        __syncthreads();
    }
    float inv = 1.f / red[0];
    __syncthreads();

    for (int kk = tid; kk < HDIM; kk += 128) {
        float acc = 0.f;
        for (int s = 0; s <= t; s++)
            acc = fmaf(sc[s], v[((size_t)b * TT + s) * HH + h * HDIM + kk], acc);
        o[rowq + kk] = acc * inv;
    }
}

// ---------------- host side ----------------
static void launch_gemm(const float* A, const float* B, const float* bias,
                        const float* res, float* C,
                        int M, int N, int K, int bmode, int relu)
{
    dim3 grid((N + BN - 1) / BN, (M + BM - 1) / BM);
    gemm_tc<<<grid, 256>>>(A, B, bias, res, C, M, N, K, bmode, relu);
}

extern "C" void kernel_launch(void* const* d_in, const int* in_sizes, int n_in,
                              void* d_out, int out_size)
{
    const int*   idx    = (const int*)  d_in[0];
    const float* tok    = (const float*)d_in[1];
    const float* pos    = (const float*)d_in[2];
    const float* Wq     = (const float*)d_in[3];
    const float* Wk     = (const float*)d_in[4];
    const float* Wv     = (const float*)d_in[5];
    const float* Wproj  = (const float*)d_in[6];
    const float* bproj  = (const float*)d_in[7];
    const float* ln1_g  = (const float*)d_in[8];
    const float* ln1_b  = (const float*)d_in[9];
    const float* ln2_g  = (const float*)d_in[10];
    const float* ln2_b  = (const float*)d_in[11];
    const float* W1     = (const float*)d_in[12];
    const float* b1     = (const float*)d_in[13];
    const float* W2     = (const float*)d_in[14];
    const float* b2     = (const float*)d_in[15];
    const float* lnf_g  = (const float*)d_in[16];
    const float* lnf_b  = (const float*)d_in[17];
    const float* Wlm    = (const float*)d_in[18];
    const float* blm    = (const float*)d_in[19];

    float *x_, *h_, *q_, *k_, *v_, *o_, *ff_;
    cudaGetSymbolAddress((void**)&x_,  g_x);
    cudaGetSymbolAddress((void**)&h_,  g_h);
    cudaGetSymbolAddress((void**)&q_,  g_q);
    cudaGetSymbolAddress((void**)&k_,  g_k);
    cudaGetSymbolAddress((void**)&v_,  g_v);
    cudaGetSymbolAddress((void**)&o_,  g_o);
    cudaGetSymbolAddress((void**)&ff_, g_ff);

    {
        int total = MM * DIM;
        embed_kernel<<<(total + 255) / 256, 256>>>(idx, tok, pos, x_);
    }

    for (int l = 0; l < LAYERS; l++) {
        const float* wq = Wq + (size_t)l * NHEAD * DIM * HDIM;
        const float* wk = Wk + (size_t)l * NHEAD * DIM * HDIM;
        const float* wv = Wv + (size_t)l * NHEAD * DIM * HDIM;
        const float* wp = Wproj + (size_t)l * HH * DIM;
        const float* bp = bproj + (size_t)l * DIM;
        const float* g1 = ln1_g + (size_t)l * DIM;
        const float* be1= ln1_b + (size_t)l * DIM;
        const float* g2 = ln2_g + (size_t)l * DIM;
        const float* be2= ln2_b + (size_t)l * DIM;
        const float* w1 = W1 + (size_t)l * DIM * FF;
        const float* bb1= b1 + (size_t)l * FF;
        const float* w2 = W2 + (size_t)l * FF * DIM;
        const float* bb2= b2 + (size_t)l * DIM;

        ln_kernel<<<MM, 256>>>(x_, g1, be1, h_);

        launch_gemm(h_, wq, nullptr, nullptr, q_, MM, HH, DIM, 1, 0);
        launch_gemm(h_, wk, nullptr, nullptr, k_, MM, HH, DIM, 1, 0);
        launch_gemm(h_, wv, nullptr, nullptr, v_, MM, HH, DIM, 1, 0);

        {
            dim3 grid(TT, NHEAD, BB);
            attn_kernel<<<grid, 128>>>(q_, k_, v_, o_);
        }

        launch_gemm(o_, wp, bp, x_, x_, MM, DIM, HH, 0, 0);

        ln_kernel<<<MM, 256>>>(x_, g2, be2, h_);

        launch_gemm(h_, w1, bb1, nullptr, ff_, MM, FF, DIM, 0, 1);

        launch_gemm(ff_, w2, bb2, x_, x_, MM, DIM, FF, 0, 0);
    }

    ln_kernel<<<MM, 256>>>(x_, lnf_g, lnf_b, h_);

    launch_gemm(h_, Wlm, blm, nullptr, (float*)d_out, MM, VOCAB, DIM, 0, 0);
}

// round 3
// speedup vs baseline: 2.0325x; 1.4624x over previous
#include <cuda_runtime.h>
#include <cuda_bf16.h>
#include <mma.h>
#include <math.h>
#include <stdint.h>

using namespace nvcuda;

// ---------------- problem constants ----------------
#define LAYERS 12
#define DIM    726
#define NHEAD  16
#define HDIM   45
#define HH     (NHEAD*HDIM)   // 720
#define TT     258
#define BB     16
#define MM     (BB*TT)        // 4128
#define FF     (4*DIM)        // 2904
#define VOCAB  50257

// ---------------- scratch ----------------
__device__ float g_x [MM*DIM];
__device__ float g_h [MM*DIM];
__device__ float g_q [MM*HH];
__device__ float g_k [MM*HH];
__device__ float g_v [MM*HH];
__device__ float g_o [MM*HH];
__device__ float g_ff[MM*FF];

// ---------------- embedding ----------------
__global__ void embed_kernel(const int* __restrict__ idx,
                             const float* __restrict__ tok,
                             const float* __restrict__ pos,
                             float* __restrict__ x)
{
    int i = blockIdx.x * blockDim.x + threadIdx.x;
    if (i >= MM * DIM) return;
    int m = i / DIM, d = i - m * DIM;
    int t = m % TT;
    x[i] = tok[idx[m] * DIM + d] + pos[t * DIM + d];
}

// ---------------- layernorm ----------------
__global__ void ln_kernel(const float* __restrict__ x,
                          const float* __restrict__ g,
                          const float* __restrict__ b,
                          float* __restrict__ h)
{
    int m = blockIdx.x;
    const float* row = x + (size_t)m * DIM;
    int tid = threadIdx.x;
    float s = 0.f, sq = 0.f;
    for (int d = tid; d < DIM; d += 256) {
        float v = row[d];
        s += v; sq += v * v;
    }
    __shared__ float r1[256], r2[256];
    r1[tid] = s; r2[tid] = sq;
    __syncthreads();
    for (int off = 128; off > 0; off >>= 1) {
        if (tid < off) { r1[tid] += r1[tid + off]; r2[tid] += r2[tid + off]; }
        __syncthreads();
    }
    float mean = r1[0] * (1.0f / DIM);
    float var  = r2[0] * (1.0f / DIM) - mean * mean;
    float rs   = rsqrtf(var + 1e-5f);
    for (int d = tid; d < DIM; d += 256)
        h[(size_t)m * DIM + d] = (row[d] - mean) * rs * g[d] + b[d];
}

// ---------------- cp.async helpers ----------------
__device__ __forceinline__ uint32_t sptr(const void* p) {
    return (uint32_t)__cvta_generic_to_shared(p);
}
__device__ __forceinline__ void cp_async4(void* dst, const void* src, bool v) {
    int sz = v ? 4 : 0;
    asm volatile("cp.async.ca.shared.global [%0], [%1], 4, %2;\n"
                 :: "r"(sptr(dst)), "l"(src), "r"(sz));
}
__device__ __forceinline__ void cp_async8(void* dst, const void* src, bool v) {
    int sz = v ? 8 : 0;
    asm volatile("cp.async.ca.shared.global [%0], [%1], 8, %2;\n"
                 :: "r"(sptr(dst)), "l"(src), "r"(sz));
}
__device__ __forceinline__ void cp_commit() {
    asm volatile("cp.async.commit_group;\n");
}
__device__ __forceinline__ void cp_wait0() {
    asm volatile("cp.async.wait_group 0;\n");
}

// ---------------- tf32 tensor-core GEMM, 128x128x16, double-buffered cp.async ----
// C[m,n] = sum_k A[m,k]*B(k,n) (+bias)(+res)(relu)
// bmode 0: B row-major [K,N];  bmode 1: QKV head layout B[(h*DIM+k)*HDIM+kk]
#define BM 128
#define BN 128
#define BK 16
#define A_LD 20
#define B_LD 132
#define STAGE_A (BM*A_LD)            // 2560
#define STAGE_B (BK*B_LD)            // 2112
#define STAGE_FLOATS (STAGE_A+STAGE_B) // 4672
#define C_LD 132

struct GemmArgs {
    const float* A; const float* Bm; const float* bias; const float* res;
    float* C; int M, N, K, bmode, relu;
};

__device__ __forceinline__ void load_A_stage(float* As, const float* A,
                                             int rm, int kb, int M, int K, int tid)
{
    // 128 x 16 floats = 1024 float2, 256 threads -> 4 iters
#pragma unroll
    for (int it = 0; it < 4; it++) {
        int lin = it * 256 + tid;
        int r = lin >> 3;
        int c = (lin & 7) * 2;
        int gm = rm + r, gk = kb + c;
        bool v = (gm < M) && (gk < K);          // K even: pair never straddles
        const float* src = A + (v ? ((size_t)gm * K + gk) : 0);
        cp_async8(&As[r * A_LD + c], src, v);
    }
}

__device__ __forceinline__ void load_B_stage(float* Bs, const GemmArgs& g,
                                             int cn, int kb, int tid)
{
    if (g.bmode == 0 && (g.N & 1) == 0) {
        // vectorized: 16 x 128 = 1024 float2
#pragma unroll
        for (int it = 0; it < 4; it++) {
            int lin = it * 256 + tid;
            int r = lin >> 6;
            int c = (lin & 63) * 2;
            int gk = kb + r, gn = cn + c;
            bool v = (gk < g.K) && (gn < g.N);
            const float* src = g.Bm + (v ? ((size_t)gk * g.N + gn) : 0);
            cp_async8(&Bs[r * B_LD + c], src, v);
        }
    } else {
        // scalar: 2048 elements
#pragma unroll
        for (int it = 0; it < 8; it++) {
            int lin = it * 256 + tid;
            int r = lin >> 7;
            int c = lin & 127;
            int gk = kb + r, gn = cn + c;
            bool v = (gk < g.K) && (gn < g.N);
            size_t off = 0;
            if (v) {
                if (g.bmode == 0) {
                    off = (size_t)gk * g.N + gn;
                } else {
                    int h  = gn / HDIM;
                    int kk = gn - h * HDIM;
                    off = ((size_t)h * DIM + gk) * HDIM + kk;
                }
            }
            cp_async4(&Bs[r * B_LD + c], g.Bm + off, v);
        }
    }
}

__device__ __forceinline__ void gemm_body(const GemmArgs& g, int bx, int by)
{
    __shared__ float smem[2 * STAGE_FLOATS];   // 37376 B

    int tid  = threadIdx.x;
    int warp = tid >> 5;
    int wm   = warp >> 1;          // 0..3
    int wn   = warp & 1;           // 0..1
    int rm   = by * BM;
    int cn   = bx * BN;

    wmma::fragment<wmma::accumulator, 16, 16, 8, float> acc[2][4];
#pragma unroll
    for (int i = 0; i < 2; i++)
#pragma unroll
        for (int j = 0; j < 4; j++)
            wmma::fill_fragment(acc[i][j], 0.f);

    int nt = (g.K + BK - 1) / BK;

    // prologue: stage 0
    load_A_stage(smem, g.A, rm, 0, g.M, g.K, tid);
    load_B_stage(smem + STAGE_A, g, cn, 0, tid);
    cp_commit();

    for (int t = 0; t < nt; t++) {
        cp_wait0();
        __syncthreads();

        int cur = t & 1;
        if (t + 1 < nt) {
            float* nA = smem + ((t + 1) & 1) * STAGE_FLOATS;
            load_A_stage(nA, g.A, rm, (t + 1) * BK, g.M, g.K, tid);
            load_B_stage(nA + STAGE_A, g, cn, (t + 1) * BK, tid);
            cp_commit();
        }

        float* As = smem + cur * STAGE_FLOATS;
        float* Bs = As + STAGE_A;

#pragma unroll
        for (int kk = 0; kk < BK; kk += 8) {
            wmma::fragment<wmma::matrix_a, 16, 16, 8, wmma::precision::tf32, wmma::row_major> af[2];
            wmma::fragment<wmma::matrix_b, 16, 16, 8, wmma::precision::tf32, wmma::row_major> bf[4];
#pragma unroll
            for (int i = 0; i < 2; i++) {
                wmma::load_matrix_sync(af[i], &As[(wm * 32 + i * 16) * A_LD + kk], A_LD);
#pragma unroll
                for (int e = 0; e < af[i].num_elements; e++)
                    af[i].x[e] = wmma::__float_to_tf32(af[i].x[e]);
            }
#pragma unroll
            for (int j = 0; j < 4; j++) {
                wmma::load_matrix_sync(bf[j], &Bs[kk * B_LD + wn * 64 + j * 16], B_LD);
#pragma unroll
                for (int e = 0; e < bf[j].num_elements; e++)
                    bf[j].x[e] = wmma::__float_to_tf32(bf[j].x[e]);
            }
#pragma unroll
            for (int i = 0; i < 2; i++)
#pragma unroll
                for (int j = 0; j < 4; j++)
                    wmma::mma_sync(acc[i][j], af[i], bf[j], acc[i][j]);
        }
        __syncthreads();
    }

    // epilogue: two half-tiles (rows 0-63, 64-127) staged through smem
    float* Cs = smem;
#pragma unroll
    for (int p = 0; p < 2; p++) {
        if ((wm >> 1) == p) {
            int lr = (wm & 1) * 32;
#pragma unroll
            for (int i = 0; i < 2; i++)
#pragma unroll
                for (int j = 0; j < 4; j++)
                    wmma::store_matrix_sync(&Cs[(lr + i * 16) * C_LD + wn * 64 + j * 16],
                                            acc[i][j], C_LD, wmma::mem_row_major);
        }
        __syncthreads();
#pragma unroll
        for (int it = 0; it < 32; it++) {
            int lin = it * 256 + tid;
            int r = lin >> 7, c = lin & 127;
            int m = rm + p * 64 + r, n = cn + c;
            if (m < g.M && n < g.N) {
                float v = Cs[r * C_LD + c];
                if (g.bias) v += g.bias[n];
                if (g.res)  v += g.res[(size_t)m * g.N + n];
                if (g.relu) v = fmaxf(v, 0.f);
                g.C[(size_t)m * g.N + n] = v;
            }
        }
        __syncthreads();
    }
}

__global__ void __launch_bounds__(256)
gemm_tc(const float* A, const float* Bm, const float* bias, const float* res,
        float* C, int M, int N, int K, int bmode, int relu)
{
    GemmArgs g{A, Bm, bias, res, C, M, N, K, bmode, relu};
    gemm_body(g, blockIdx.x, blockIdx.y);
}

// fused QKV: blockIdx.z selects weight/output
__global__ void __launch_bounds__(256)
gemm_qkv(const float* A,
         const float* wq, const float* wk, const float* wv,
         float* q, float* k, float* v)
{
    const float* Bm = (blockIdx.z == 0) ? wq : (blockIdx.z == 1) ? wk : wv;
    float* C = (blockIdx.z == 0) ? q : (blockIdx.z == 1) ? k : v;
    GemmArgs g{A, Bm, nullptr, nullptr, C, MM, HH, DIM, 1, 0};
    gemm_body(g, blockIdx.x, blockIdx.y);
}

// ---------------- fused causal attention ----------------
__global__ void attn_kernel(const float* __restrict__ q,
                            const float* __restrict__ k,
                            const float* __restrict__ v,
                            float* __restrict__ o)
{
    int t = blockIdx.x, h = blockIdx.y, b = blockIdx.z;
    int tid = threadIdx.x;

    __shared__ float sc[TT];
    __shared__ float red[128];
    __shared__ float qs[HDIM];

    const float scale = rsqrtf((float)HDIM);
    size_t rowq = ((size_t)b * TT + t) * HH + h * HDIM;

    if (tid < HDIM) qs[tid] = q[rowq + tid];
    __syncthreads();

    for (int s = tid; s <= t; s += 128) {
        const float* krow = k + ((size_t)b * TT + s) * HH + h * HDIM;
        float d = 0.f;
#pragma unroll
        for (int kk = 0; kk < HDIM; kk++) d = fmaf(qs[kk], krow[kk], d);
        sc[s] = d * scale;
    }
    __syncthreads();

    float mx = -1e30f;
    for (int s = tid; s <= t; s += 128) mx = fmaxf(mx, sc[s]);
    red[tid] = mx;
    __syncthreads();
    for (int off = 64; off > 0; off >>= 1) {
        if (tid < off) red[tid] = fmaxf(red[tid], red[tid + off]);
        __syncthreads();
    }
    float gmax = red[0];
    __syncthreads();

    float sum = 0.f;
    for (int s = tid; s <= t; s += 128) {
        float e = expf(sc[s] - gmax);
        sc[s] = e;
        sum += e;
    }
    red[tid] = sum;
    __syncthreads();
    for (int off = 64; off > 0; off >>= 1) {
        if (tid < off) red[tid] += red[tid + off];
        __syncthreads();
    }
    float inv = 1.f / red[0];
    __syncthreads();

    if (tid < HDIM) {
        const float* vb = v + ((size_t)b * TT) * HH + h * HDIM + tid;
        float a0 = 0.f, a1 = 0.f, a2 = 0.f, a3 = 0.f;
        int s = 0;
        for (; s + 3 <= t; s += 4) {
            a0 = fmaf(sc[s],     vb[(size_t)(s)     * HH], a0);
            a1 = fmaf(sc[s + 1], vb[(size_t)(s + 1) * HH], a1);
            a2 = fmaf(sc[s + 2], vb[(size_t)(s + 2) * HH], a2);
            a3 = fmaf(sc[s + 3], vb[(size_t)(s + 3) * HH], a3);
        }
        for (; s <= t; s++)
            a0 = fmaf(sc[s], vb[(size_t)s * HH], a0);
        o[rowq + tid] = ((a0 + a1) + (a2 + a3)) * inv;
    }
}

// ---------------- host side ----------------
static void launch_gemm(const float* A, const float* B, const float* bias,
                        const float* res, float* C,
                        int M, int N, int K, int bmode, int relu)
{
    dim3 grid((N + BN - 1) / BN, (M + BM - 1) / BM);
    gemm_tc<<<grid, 256>>>(A, B, bias, res, C, M, N, K, bmode, relu);
}

extern "C" void kernel_launch(void* const* d_in, const int* in_sizes, int n_in,
                              void* d_out, int out_size)
{
    const int*   idx    = (const int*)  d_in[0];
    const float* tok    = (const float*)d_in[1];
    const float* pos    = (const float*)d_in[2];
    const float* Wq     = (const float*)d_in[3];
    const float* Wk     = (const float*)d_in[4];
    const float* Wv     = (const float*)d_in[5];
    const float* Wproj  = (const float*)d_in[6];
    const float* bproj  = (const float*)d_in[7];
    const float* ln1_g  = (const float*)d_in[8];
    const float* ln1_b  = (const float*)d_in[9];
    const float* ln2_g  = (const float*)d_in[10];
    const float* ln2_b  = (const float*)d_in[11];
    const float* W1     = (const float*)d_in[12];
    const float* b1     = (const float*)d_in[13];
    const float* W2     = (const float*)d_in[14];
    const float* b2     = (const float*)d_in[15];
    const float* lnf_g  = (const float*)d_in[16];
    const float* lnf_b  = (const float*)d_in[17];
    const float* Wlm    = (const float*)d_in[18];
    const float* blm    = (const float*)d_in[19];

    float *x_, *h_, *q_, *k_, *v_, *o_, *ff_;
    cudaGetSymbolAddress((void**)&x_,  g_x);
    cudaGetSymbolAddress((void**)&h_,  g_h);
    cudaGetSymbolAddress((void**)&q_,  g_q);
    cudaGetSymbolAddress((void**)&k_,  g_k);
    cudaGetSymbolAddress((void**)&v_,  g_v);
    cudaGetSymbolAddress((void**)&o_,  g_o);
    cudaGetSymbolAddress((void**)&ff_, g_ff);

    {
        int total = MM * DIM;
        embed_kernel<<<(total + 255) / 256, 256>>>(idx, tok, pos, x_);
    }

    for (int l = 0; l < LAYERS; l++) {
        const float* wq = Wq + (size_t)l * NHEAD * DIM * HDIM;
        const float* wk = Wk + (size_t)l * NHEAD * DIM * HDIM;
        const float* wv = Wv + (size_t)l * NHEAD * DIM * HDIM;
        const float* wp = Wproj + (size_t)l * HH * DIM;
        const float* bp = bproj + (size_t)l * DIM;
        const float* g1 = ln1_g + (size_t)l * DIM;
        const float* be1= ln1_b + (size_t)l * DIM;
        const float* g2 = ln2_g + (size_t)l * DIM;
        const float* be2= ln2_b + (size_t)l * DIM;
        const float* w1 = W1 + (size_t)l * DIM * FF;
        const float* bb1= b1 + (size_t)l * FF;
        const float* w2 = W2 + (size_t)l * FF * DIM;
        const float* bb2= b2 + (size_t)l * DIM;

        ln_kernel<<<MM, 256>>>(x_, g1, be1, h_);

        {
            dim3 grid((HH + BN - 1) / BN, (MM + BM - 1) / BM, 3);
            gemm_qkv<<<grid, 256>>>(h_, wq, wk, wv, q_, k_, v_);
        }

        {
            dim3 grid(TT, NHEAD, BB);
            attn_kernel<<<grid, 128>>>(q_, k_, v_, o_);
        }

        launch_gemm(o_, wp, bp, x_, x_, MM, DIM, HH, 0, 0);

        ln_kernel<<<MM, 256>>>(x_, g2, be2, h_);

        launch_gemm(h_, w1, bb1, nullptr, ff_, MM, FF, DIM, 0, 1);

        launch_gemm(ff_, w2, bb2, x_, x_, MM, DIM, FF, 0, 0);
    }

    ln_kernel<<<MM, 256>>>(x_, lnf_g, lnf_b, h_);

    launch_gemm(h_, Wlm, blm, nullptr, (float*)d_out, MM, VOCAB, DIM, 0, 0);
}

// round 4
// speedup vs baseline: 2.7554x; 1.3557x over previous
#include <cuda_runtime.h>
#include <cuda_bf16.h>
#include <mma.h>
#include <math.h>
#include <stdint.h>

using namespace nvcuda;

// ---------------- problem constants ----------------
#define LAYERS 12
#define DIM    726
#define NHEAD  16
#define HDIM   45
#define HH     (NHEAD*HDIM)   // 720
#define TT     258
#define BB     16
#define MM     (BB*TT)        // 4128
#define FF     (4*DIM)        // 2904
#define VOCAB  50257

// ---------------- scratch ----------------
__device__ float g_x [MM*DIM];
__device__ float g_h [MM*DIM];
__device__ float g_q [MM*HH];   // [B,H,T,HD]
__device__ float g_k [MM*HH];   // [B,H,T,HD]
__device__ float g_v [MM*HH];   // [B,H,T,HD]
__device__ float g_o [MM*HH];   // [M, HH]
__device__ float g_ff[MM*FF];

// ---------------- embedding ----------------
__global__ void embed_kernel(const int* __restrict__ idx,
                             const float* __restrict__ tok,
                             const float* __restrict__ pos,
                             float* __restrict__ x)
{
    int i = blockIdx.x * blockDim.x + threadIdx.x;
    if (i >= MM * DIM) return;
    int m = i / DIM, d = i - m * DIM;
    int t = m % TT;
    x[i] = tok[idx[m] * DIM + d] + pos[t * DIM + d];
}

// ---------------- layernorm ----------------
__global__ void ln_kernel(const float* __restrict__ x,
                          const float* __restrict__ g,
                          const float* __restrict__ b,
                          float* __restrict__ h)
{
    int m = blockIdx.x;
    const float* row = x + (size_t)m * DIM;
    int tid = threadIdx.x;
    float s = 0.f, sq = 0.f;
    for (int d = tid; d < DIM; d += 256) {
        float v = row[d];
        s += v; sq += v * v;
    }
    __shared__ float r1[256], r2[256];
    r1[tid] = s; r2[tid] = sq;
    __syncthreads();
    for (int off = 128; off > 0; off >>= 1) {
        if (tid < off) { r1[tid] += r1[tid + off]; r2[tid] += r2[tid + off]; }
        __syncthreads();
    }
    float mean = r1[0] * (1.0f / DIM);
    float var  = r2[0] * (1.0f / DIM) - mean * mean;
    float rs   = rsqrtf(var + 1e-5f);
    for (int d = tid; d < DIM; d += 256)
        h[(size_t)m * DIM + d] = (row[d] - mean) * rs * g[d] + b[d];
}

// ---------------- cp.async helpers ----------------
__device__ __forceinline__ uint32_t sptr(const void* p) {
    return (uint32_t)__cvta_generic_to_shared(p);
}
__device__ __forceinline__ void cp_async4(void* dst, const void* src, bool v) {
    int sz = v ? 4 : 0;
    asm volatile("cp.async.ca.shared.global [%0], [%1], 4, %2;\n"
                 :: "r"(sptr(dst)), "l"(src), "r"(sz));
}
__device__ __forceinline__ void cp_async8(void* dst, const void* src, bool v) {
    int sz = v ? 8 : 0;
    asm volatile("cp.async.ca.shared.global [%0], [%1], 8, %2;\n"
                 :: "r"(sptr(dst)), "l"(src), "r"(sz));
}
__device__ __forceinline__ void cp_commit() {
    asm volatile("cp.async.commit_group;\n");
}
__device__ __forceinline__ void cp_wait0() {
    asm volatile("cp.async.wait_group 0;\n");
}

// ---------------- tf32 tensor-core GEMM, 128x128x16, double-buffered cp.async ----
// C[m,n] = sum_k A[m,k]*B(k,n) (+bias)(+res)(relu)
// bmode 0: B row-major [K,N];  bmode 1: QKV head layout B[(h*DIM+k)*HDIM+kk]
// cmode 0: C row-major [M,N];  cmode 1: scatter to [B,H,T,HD] (QKV outputs)
#define BM 128
#define BN 128
#define BK 16
#define A_LD 20
#define B_LD 132
#define STAGE_A (BM*A_LD)
#define STAGE_B (BK*B_LD)
#define STAGE_FLOATS (STAGE_A+STAGE_B)
#define C_LD 132

struct GemmArgs {
    const float* A; const float* Bm; const float* bias; const float* res;
    float* C; int M, N, K, bmode, relu, cmode;
};

__device__ __forceinline__ void load_A_stage(float* As, const float* A,
                                             int rm, int kb, int M, int K, int tid)
{
#pragma unroll
    for (int it = 0; it < 4; it++) {
        int lin = it * 256 + tid;
        int r = lin >> 3;
        int c = (lin & 7) * 2;
        int gm = rm + r, gk = kb + c;
        bool v = (gm < M) && (gk < K);
        const float* src = A + (v ? ((size_t)gm * K + gk) : 0);
        cp_async8(&As[r * A_LD + c], src, v);
    }
}

__device__ __forceinline__ void load_B_stage(float* Bs, const GemmArgs& g,
                                             int cn, int kb, int tid)
{
    if (g.bmode == 0 && (g.N & 1) == 0) {
#pragma unroll
        for (int it = 0; it < 4; it++) {
            int lin = it * 256 + tid;
            int r = lin >> 6;
            int c = (lin & 63) * 2;
            int gk = kb + r, gn = cn + c;
            bool v = (gk < g.K) && (gn < g.N);
            const float* src = g.Bm + (v ? ((size_t)gk * g.N + gn) : 0);
            cp_async8(&Bs[r * B_LD + c], src, v);
        }
    } else {
#pragma unroll
        for (int it = 0; it < 8; it++) {
            int lin = it * 256 + tid;
            int r = lin >> 7;
            int c = lin & 127;
            int gk = kb + r, gn = cn + c;
            bool v = (gk < g.K) && (gn < g.N);
            size_t off = 0;
            if (v) {
                if (g.bmode == 0) {
                    off = (size_t)gk * g.N + gn;
                } else {
                    int h  = gn / HDIM;
                    int kk = gn - h * HDIM;
                    off = ((size_t)h * DIM + gk) * HDIM + kk;
                }
            }
            cp_async4(&Bs[r * B_LD + c], g.Bm + off, v);
        }
    }
}

__device__ __forceinline__ void gemm_body(const GemmArgs& g, int bx, int by)
{
    __shared__ float smem[2 * STAGE_FLOATS];

    int tid  = threadIdx.x;
    int warp = tid >> 5;
    int wm   = warp >> 1;
    int wn   = warp & 1;
    int rm   = by * BM;
    int cn   = bx * BN;

    wmma::fragment<wmma::accumulator, 16, 16, 8, float> acc[2][4];
#pragma unroll
    for (int i = 0; i < 2; i++)
#pragma unroll
        for (int j = 0; j < 4; j++)
            wmma::fill_fragment(acc[i][j], 0.f);

    int nt = (g.K + BK - 1) / BK;

    load_A_stage(smem, g.A, rm, 0, g.M, g.K, tid);
    load_B_stage(smem + STAGE_A, g, cn, 0, tid);
    cp_commit();

    for (int t = 0; t < nt; t++) {
        cp_wait0();
        __syncthreads();

        int cur = t & 1;
        if (t + 1 < nt) {
            float* nA = smem + ((t + 1) & 1) * STAGE_FLOATS;
            load_A_stage(nA, g.A, rm, (t + 1) * BK, g.M, g.K, tid);
            load_B_stage(nA + STAGE_A, g, cn, (t + 1) * BK, tid);
            cp_commit();
        }

        float* As = smem + cur * STAGE_FLOATS;
        float* Bs = As + STAGE_A;

#pragma unroll
        for (int kk = 0; kk < BK; kk += 8) {
            wmma::fragment<wmma::matrix_a, 16, 16, 8, wmma::precision::tf32, wmma::row_major> af[2];
            wmma::fragment<wmma::matrix_b, 16, 16, 8, wmma::precision::tf32, wmma::row_major> bf[4];
#pragma unroll
            for (int i = 0; i < 2; i++) {
                wmma::load_matrix_sync(af[i], &As[(wm * 32 + i * 16) * A_LD + kk], A_LD);
#pragma unroll
                for (int e = 0; e < af[i].num_elements; e++)
                    af[i].x[e] = wmma::__float_to_tf32(af[i].x[e]);
            }
#pragma unroll
            for (int j = 0; j < 4; j++) {
                wmma::load_matrix_sync(bf[j], &Bs[kk * B_LD + wn * 64 + j * 16], B_LD);
#pragma unroll
                for (int e = 0; e < bf[j].num_elements; e++)
                    bf[j].x[e] = wmma::__float_to_tf32(bf[j].x[e]);
            }
#pragma unroll
            for (int i = 0; i < 2; i++)
#pragma unroll
                for (int j = 0; j < 4; j++)
                    wmma::mma_sync(acc[i][j], af[i], bf[j], acc[i][j]);
        }
        __syncthreads();
    }

    float* Cs = smem;
#pragma unroll
    for (int p = 0; p < 2; p++) {
        if ((wm >> 1) == p) {
            int lr = (wm & 1) * 32;
#pragma unroll
            for (int i = 0; i < 2; i++)
#pragma unroll
                for (int j = 0; j < 4; j++)
                    wmma::store_matrix_sync(&Cs[(lr + i * 16) * C_LD + wn * 64 + j * 16],
                                            acc[i][j], C_LD, wmma::mem_row_major);
        }
        __syncthreads();
#pragma unroll
        for (int it = 0; it < 32; it++) {
            int lin = it * 256 + tid;
            int r = lin >> 7, c = lin & 127;
            int m = rm + p * 64 + r, n = cn + c;
            if (m < g.M && n < g.N) {
                float v = Cs[r * C_LD + c];
                if (g.bias) v += g.bias[n];
                if (g.res)  v += g.res[(size_t)m * g.N + n];
                if (g.relu) v = fmaxf(v, 0.f);
                if (g.cmode == 1) {
                    int bb = m / TT, t = m - bb * TT;
                    int hh = n / HDIM, kk = n - hh * HDIM;
                    g.C[(((size_t)bb * NHEAD + hh) * TT + t) * HDIM + kk] = v;
                } else {
                    g.C[(size_t)m * g.N + n] = v;
                }
            }
        }
        __syncthreads();
    }
}

__global__ void __launch_bounds__(256)
gemm_tc(const float* A, const float* Bm, const float* bias, const float* res,
        float* C, int M, int N, int K, int bmode, int relu)
{
    GemmArgs g{A, Bm, bias, res, C, M, N, K, bmode, relu, 0};
    gemm_body(g, blockIdx.x, blockIdx.y);
}

__global__ void __launch_bounds__(256)
gemm_qkv(const float* A,
         const float* wq, const float* wk, const float* wv,
         float* q, float* k, float* v)
{
    const float* Bm = (blockIdx.z == 0) ? wq : (blockIdx.z == 1) ? wk : wv;
    float* C = (blockIdx.z == 0) ? q : (blockIdx.z == 1) ? k : v;
    GemmArgs g{A, Bm, nullptr, nullptr, C, MM, HH, DIM, 1, 0, 1};
    gemm_body(g, blockIdx.x, blockIdx.y);
}

// ---------------- tiled causal attention ----------------
// q,k,v in [B,H,T,HD]; o written to [M, HH] (m = b*T+t, col = h*HD+kk)
#define QT 16
#define SK 64
#define KV_LD 47
#define SC_LD 260

__global__ void __launch_bounds__(256)
attn_tile(const float* __restrict__ q,
          const float* __restrict__ k,
          const float* __restrict__ v,
          float* __restrict__ o)
{
    int qt = blockIdx.x;            // query tile
    int h  = blockIdx.y;
    int b  = blockIdx.z;
    int tid  = threadIdx.x;
    int lane = tid & 31;
    int warp = tid >> 5;

    __shared__ float qs[QT * KV_LD];
    __shared__ float kv[SK * KV_LD];
    __shared__ float sc[QT * SC_LD];

    const float scale = rsqrtf((float)HDIM);
    int t0 = qt * QT;
    int s_hi = min(t0 + QT, TT);    // exclusive upper bound on key index

    size_t headbase = ((size_t)b * NHEAD + h) * TT * HDIM;
    const float* qh = q + headbase;
    const float* kh = k + headbase;
    const float* vh = v + headbase;

    // load Q tile (rows t0..t0+QT)
    for (int i = tid; i < QT * HDIM; i += 256) {
        int r = i / HDIM, d = i - r * HDIM;
        int t = t0 + r;
        qs[r * KV_LD + d] = (t < TT) ? qh[(size_t)t * HDIM + d] : 0.f;
    }

    // ---- pass 1: scores ----
    for (int c0 = 0; c0 < s_hi; c0 += SK) {
        int rows = min(SK, TT - c0);
        __syncthreads();
        // linear copy: global rows contiguous in [T,HD]
        for (int i = tid; i < rows * HDIM; i += 256) {
            int r = i / HDIM, d = i - r * HDIM;
            kv[r * KV_LD + d] = kh[(size_t)(c0) * HDIM + i];
        }
        __syncthreads();
#pragma unroll
        for (int it = 0; it < 4; it++) {
            int lin = it * 256 + tid;
            int qq = lin >> 6;
            int sl = lin & 63;
            int s = c0 + sl;
            if (s < s_hi) {
                const float* qr = &qs[qq * KV_LD];
                const float* kr = &kv[sl * KV_LD];
                float d = 0.f;
#pragma unroll
                for (int kk2 = 0; kk2 < HDIM; kk2++)
                    d = fmaf(qr[kk2], kr[kk2], d);
                sc[qq * SC_LD + s] = d * scale;
            }
        }
    }
    __syncthreads();

    // ---- softmax per query row (2 rows per warp) ----
#pragma unroll
    for (int rr = 0; rr < 2; rr++) {
        int qq = warp * 2 + rr;
        int t = t0 + qq;
        if (t < TT) {
            float* row = &sc[qq * SC_LD];
            int len = t + 1;               // causal: s <= t
            float mx = -1e30f;
            for (int s = lane; s < len; s += 32) mx = fmaxf(mx, row[s]);
#pragma unroll
            for (int off = 16; off > 0; off >>= 1)
                mx = fmaxf(mx, __shfl_xor_sync(0xffffffff, mx, off));
            float sum = 0.f;
            for (int s = lane; s < len; s += 32) {
                float e = expf(row[s] - mx);
                row[s] = e;
                sum += e;
            }
#pragma unroll
            for (int off = 16; off > 0; off >>= 1)
                sum += __shfl_xor_sync(0xffffffff, sum, off);
            float inv = 1.f / sum;
            for (int s = lane; s < len; s += 32) row[s] *= inv;
            for (int s = len + lane; s < s_hi; s += 32) row[s] = 0.f;
        }
    }
    __syncthreads();

    // ---- pass 2: AV ----
    float acc[3] = {0.f, 0.f, 0.f};
    for (int c0 = 0; c0 < s_hi; c0 += SK) {
        int rows = min(SK, TT - c0);
        int srows = min(rows, s_hi - c0);
        __syncthreads();
        for (int i = tid; i < rows * HDIM; i += 256) {
            int r = i / HDIM, d = i - r * HDIM;
            kv[r * KV_LD + d] = vh[(size_t)(c0) * HDIM + i];
        }
        __syncthreads();
#pragma unroll
        for (int it = 0; it < 3; it++) {
            int lin = it * 256 + tid;
            if (lin < QT * HDIM) {
                int qq = lin / HDIM;
                int kk2 = lin - qq * HDIM;
                const float* row = &sc[qq * SC_LD + c0];
                float a = acc[it];
                for (int sl = 0; sl < srows; sl++)
                    a = fmaf(row[sl], kv[sl * KV_LD + kk2], a);
                acc[it] = a;
            }
        }
    }

    // ---- write O in [M, HH] layout ----
#pragma unroll
    for (int it = 0; it < 3; it++) {
        int lin = it * 256 + tid;
        if (lin < QT * HDIM) {
            int qq = lin / HDIM;
            int kk2 = lin - qq * HDIM;
            int t = t0 + qq;
            if (t < TT)
                o[((size_t)b * TT + t) * HH + h * HDIM + kk2] = acc[it];
        }
    }
}

// ---------------- host side ----------------
static void launch_gemm(const float* A, const float* B, const float* bias,
                        const float* res, float* C,
                        int M, int N, int K, int bmode, int relu)
{
    dim3 grid((N + BN - 1) / BN, (M + BM - 1) / BM);
    gemm_tc<<<grid, 256>>>(A, B, bias, res, C, M, N, K, bmode, relu);
}

extern "C" void kernel_launch(void* const* d_in, const int* in_sizes, int n_in,
                              void* d_out, int out_size)
{
    const int*   idx    = (const int*)  d_in[0];
    const float* tok    = (const float*)d_in[1];
    const float* pos    = (const float*)d_in[2];
    const float* Wq     = (const float*)d_in[3];
    const float* Wk     = (const float*)d_in[4];
    const float* Wv     = (const float*)d_in[5];
    const float* Wproj  = (const float*)d_in[6];
    const float* bproj  = (const float*)d_in[7];
    const float* ln1_g  = (const float*)d_in[8];
    const float* ln1_b  = (const float*)d_in[9];
    const float* ln2_g  = (const float*)d_in[10];
    const float* ln2_b  = (const float*)d_in[11];
    const float* W1     = (const float*)d_in[12];
    const float* b1     = (const float*)d_in[13];
    const float* W2     = (const float*)d_in[14];
    const float* b2     = (const float*)d_in[15];
    const float* lnf_g  = (const float*)d_in[16];
    const float* lnf_b  = (const float*)d_in[17];
    const float* Wlm    = (const float*)d_in[18];
    const float* blm    = (const float*)d_in[19];

    float *x_, *h_, *q_, *k_, *v_, *o_, *ff_;
    cudaGetSymbolAddress((void**)&x_,  g_x);
    cudaGetSymbolAddress((void**)&h_,  g_h);
    cudaGetSymbolAddress((void**)&q_,  g_q);
    cudaGetSymbolAddress((void**)&k_,  g_k);
    cudaGetSymbolAddress((void**)&v_,  g_v);
    cudaGetSymbolAddress((void**)&o_,  g_o);
    cudaGetSymbolAddress((void**)&ff_, g_ff);

    {
        int total = MM * DIM;
        embed_kernel<<<(total + 255) / 256, 256>>>(idx, tok, pos, x_);
    }

    for (int l = 0; l < LAYERS; l++) {
        const float* wq = Wq + (size_t)l * NHEAD * DIM * HDIM;
        const float* wk = Wk + (size_t)l * NHEAD * DIM * HDIM;
        const float* wv = Wv + (size_t)l * NHEAD * DIM * HDIM;
        const float* wp = Wproj + (size_t)l * HH * DIM;
        const float* bp = bproj + (size_t)l * DIM;
        const float* g1 = ln1_g + (size_t)l * DIM;
        const float* be1= ln1_b + (size_t)l * DIM;
        const float* g2 = ln2_g + (size_t)l * DIM;
        const float* be2= ln2_b + (size_t)l * DIM;
        const float* w1 = W1 + (size_t)l * DIM * FF;
        const float* bb1= b1 + (size_t)l * FF;
        const float* w2 = W2 + (size_t)l * FF * DIM;
        const float* bb2= b2 + (size_t)l * DIM;

        ln_kernel<<<MM, 256>>>(x_, g1, be1, h_);

        {
            dim3 grid((HH + BN - 1) / BN, (MM + BM - 1) / BM, 3);
            gemm_qkv<<<grid, 256>>>(h_, wq, wk, wv, q_, k_, v_);
        }

        {
            dim3 grid((TT + QT - 1) / QT, NHEAD, BB);
            attn_tile<<<grid, 256>>>(q_, k_, v_, o_);
        }

        launch_gemm(o_, wp, bp, x_, x_, MM, DIM, HH, 0, 0);

        ln_kernel<<<MM, 256>>>(x_, g2, be2, h_);

        launch_gemm(h_, w1, bb1, nullptr, ff_, MM, FF, DIM, 0, 1);

        launch_gemm(ff_, w2, bb2, x_, x_, MM, DIM, FF, 0, 0);
    }

    ln_kernel<<<MM, 256>>>(x_, lnf_g, lnf_b, h_);

    launch_gemm(h_, Wlm, blm, nullptr, (float*)d_out, MM, VOCAB, DIM, 0, 0);
}